// round 15
// baseline (speedup 1.0000x reference)
#include <cuda_runtime.h>
#include <cuda_bf16.h>
#include <cuda_fp16.h>
#include <math.h>
#include <stdint.h>

// ---------------- problem constants ----------------
#define B_   2
#define S_   1024
#define H_   1024
#define NH_  16
#define NKV_ 4
#define HD_  64
#define E_   8
#define TOPK_ 2
#define I_   3584
#define T_   (B_ * S_)
#define EPS_ 1e-5f
#define QKVN 1536
#define NQW  (H_ * NH_ * HD_)
#define NKW  (H_ * NKV_ * HD_)

// ---------------- fp32 scratch ----------------
__device__ float g_hidden[T_ * H_];
__device__ float g_xn[T_ * H_];
__device__ float g_downo[(long long)T_ * TOPK_ * H_];
__device__ int   g_cnt[E_];
__device__ int   g_tok[E_ * T_];
__device__ int   g_pairm[E_ * T_];
__device__ float g_pairw[T_ * TOPK_];

// ---------------- fp16 planes ----------------
__device__ __half h_x[T_ * H_];
__device__ __half h_qkv[T_ * QKVN];
__device__ __half h_wqkv[H_ * QKVN];
__device__ __half h_at[T_ * H_];
__device__ __half h_wo[NH_ * HD_ * H_];
__device__ __half h_xn[T_ * H_];
__device__ __half h_act[(long long)T_ * TOPK_ * I_];

// ---------------- merged small weight conversion (wq|wk|wv -> packed, wo) --
__global__ void convw_kernel(const float* __restrict__ wq, const float* __restrict__ wk,
                             const float* __restrict__ wv, const float* __restrict__ wo,
                             __half* __restrict__ dqkv, __half* __restrict__ dwo) {
    long long idx = ((long long)blockIdx.x * 256 + threadIdx.x) * 4;
    const long long n1 = NQW, n2 = n1 + NKW, n3 = n2 + NKW, n4 = n3 + NQW;
    if (idx >= n4) return;
    if (idx >= n3) {
        long long i = idx - n3;
        float4 v = *(const float4*)(wo + i);
        *(__half2*)(dwo + i)     = __floats2half2_rn(v.x, v.y);
        *(__half2*)(dwo + i + 2) = __floats2half2_rn(v.z, v.w);
        return;
    }
    const float* src;
    long long i;
    int ncols, doff;
    if (idx < n1)      { src = wq; i = idx;      ncols = 1024; doff = 0; }
    else if (idx < n2) { src = wk; i = idx - n1; ncols = 256;  doff = 1024; }
    else               { src = wv; i = idx - n2; ncols = 256;  doff = 1280; }
    int row = (int)(i / ncols), col = (int)(i % ncols);
    float4 v = *(const float4*)(src + i);
    long long d = (long long)row * QKVN + doff + col;
    *(__half2*)(dqkv + d)     = __floats2half2_rn(v.x, v.y);
    *(__half2*)(dqkv + d + 2) = __floats2half2_rn(v.z, v.w);
}

// ---------------- RMSNorm ----------------
__global__ void rmsnorm_kernel(const float* __restrict__ X, const float* __restrict__ w,
                               float* __restrict__ Yf, __half* __restrict__ Y16) {
    int t = blockIdx.x;
    const float* x = X + (long long)t * H_;
    float ss = 0.f;
    for (int i = threadIdx.x; i < H_; i += 256) { float v = x[i]; ss = fmaf(v, v, ss); }
    #pragma unroll
    for (int o = 16; o; o >>= 1) ss += __shfl_xor_sync(~0u, ss, o);
    __shared__ float red[8];
    __shared__ float rs;
    if ((threadIdx.x & 31) == 0) red[threadIdx.x >> 5] = ss;
    __syncthreads();
    if (threadIdx.x == 0) {
        float s = 0.f;
        #pragma unroll
        for (int i = 0; i < 8; i++) s += red[i];
        rs = rsqrtf(s / (float)H_ + EPS_);
    }
    __syncthreads();
    float r = rs;
    for (int i = threadIdx.x; i < H_; i += 256) {
        float y = x[i] * r * w[i];
        if (Yf) Yf[(long long)t * H_ + i] = y;
        Y16[(long long)t * H_ + i] = __float2half_rn(y);
    }
}

// ---------------- tile constants ----------------
#define GBM 128
#define GBN 128
#define BSTRIDE 136
#define HGBK 64
#define HASTRIDE 72
#define HA_PLANE (GBM * HASTRIDE)
#define HB_PLANE (HGBK * BSTRIDE)
#define HSTAGE (HA_PLANE + HB_PLANE)
#define HSMEM2 (2 * HSTAGE * 2)

#define MMAH16816(d, a, b)                                                      \
    asm volatile("mma.sync.aligned.m16n8k16.row.col.f32.f16.f16.f32 "           \
                 "{%0,%1,%2,%3}, {%4,%5,%6,%7}, {%8,%9}, {%0,%1,%2,%3};"        \
                 : "+f"((d)[0]), "+f"((d)[1]), "+f"((d)[2]), "+f"((d)[3])       \
                 : "r"((a)[0]), "r"((a)[1]), "r"((a)[2]), "r"((a)[3]),          \
                   "r"((b)[0]), "r"((b)[1]))

__device__ __forceinline__ void cp16(uint32_t dst, const void* src, int use) {
    asm volatile("cp.async.cg.shared.global [%0], [%1], 16, %2;"
                 :: "r"(dst), "l"(src), "r"(use));
}

// one ks16-step of the 128x128 warp-tiled HMMA
__device__ __forceinline__ void mma_step64(uint32_t sA, uint32_t sB, int ks,
                                           int wm, int wn, int lane,
                                           float (*acc)[4][4]) {
    uint32_t af[4][4], bf[4][2];
    #pragma unroll
    for (int mi = 0; mi < 4; mi++) {
        uint32_t off = ((wm * 64 + mi * 16 + (lane & 15)) * HASTRIDE + ks + (lane >> 4) * 8) * 2;
        asm volatile("ldmatrix.sync.aligned.m8n8.x4.shared.b16 {%0,%1,%2,%3}, [%4];"
                     : "=r"(af[mi][0]), "=r"(af[mi][1]), "=r"(af[mi][2]), "=r"(af[mi][3])
                     : "r"(sA + off));
    }
    #pragma unroll
    for (int pp = 0; pp < 2; pp++) {
        uint32_t off = ((ks + (lane & 15)) * BSTRIDE + wn * 32 + pp * 16 + (lane >> 4) * 8) * 2;
        asm volatile("ldmatrix.sync.aligned.m8n8.x4.trans.shared.b16 {%0,%1,%2,%3}, [%4];"
                     : "=r"(bf[2 * pp][0]), "=r"(bf[2 * pp][1]),
                       "=r"(bf[2 * pp + 1][0]), "=r"(bf[2 * pp + 1][1])
                     : "r"(sB + off));
    }
    #pragma unroll
    for (int mi = 0; mi < 4; mi++)
        #pragma unroll
        for (int ni = 0; ni < 4; ni++)
            MMAH16816(acc[mi][ni], af[mi], bf[ni]);
}

// ---------------- QKV GEMM with fused RoPE + fp16 epilogue ----------------
__global__ __launch_bounds__(256, 2)
void gemm_qkv_kernel(const __half* __restrict__ A, const __half* __restrict__ W,
                     __half* __restrict__ Oq, int M, int N, int K) {
    int m0 = blockIdx.y * GBM;
    int n0 = blockIdx.x * GBN;

    extern __shared__ __half hsmem[];
    const uint32_t smem_b = (uint32_t)__cvta_generic_to_shared(hsmem);

    const int tid = threadIdx.x;
    const int lane = tid & 31;
    const int warp = tid >> 5;
    const int wm = warp >> 2;
    const int wn = warp & 3;

    const int ar = tid >> 1;
    const int ac4 = (tid & 1) * 4;
    const __half* aptr = A + (long long)(m0 + ar) * K + ac4 * 8;
    const int br = tid >> 4, bc16 = tid & 15;
    const __half* b_base = W + n0 + bc16 * 8;

    const int nk = K / HGBK;

    auto prefetch = [&](int ki, int s) {
        uint32_t st = smem_b + s * HSTAGE * 2;
        int k0 = ki * HGBK;
        uint32_t dA = st + (ar * HASTRIDE + ac4 * 8) * 2;
        #pragma unroll
        for (int j = 0; j < 4; j++)
            cp16(dA + j * 16, aptr + k0 + j * 8, 16);
        uint32_t dB = st + (HA_PLANE + br * BSTRIDE + bc16 * 8) * 2;
        #pragma unroll
        for (int j = 0; j < 4; j++)
            cp16(dB + j * 16 * BSTRIDE * 2, b_base + (long long)(k0 + br + j * 16) * N, 16);
        asm volatile("cp.async.commit_group;");
    };

    float acc[4][4][4];
    #pragma unroll
    for (int mi = 0; mi < 4; mi++)
        #pragma unroll
        for (int ni = 0; ni < 4; ni++)
            #pragma unroll
            for (int r = 0; r < 4; r++) acc[mi][ni][r] = 0.f;

    prefetch(0, 0);

    for (int i = 0; i < nk; i++) {
        if (i + 1 < nk) {
            prefetch(i + 1, (i + 1) & 1);
            asm volatile("cp.async.wait_group 1;");
        } else {
            asm volatile("cp.async.wait_group 0;");
        }
        __syncthreads();

        uint32_t st = smem_b + (i & 1) * HSTAGE * 2;
        mma_step64(st, st + HA_PLANE * 2, 0,  wm, wn, lane, acc);
        mma_step64(st, st + HA_PLANE * 2, 16, wm, wn, lane, acc);
        mma_step64(st, st + HA_PLANE * 2, 32, wm, wn, lane, acc);
        mma_step64(st, st + HA_PLANE * 2, 48, wm, wn, lane, acc);
        __syncthreads();
    }

    // ---- stage fp32 tile in smem ----
    float* Csm = (float*)hsmem;   // 128 x 132 floats = 67584 B
    const int g = lane >> 2, tg = lane & 3;
    #pragma unroll
    for (int mi = 0; mi < 4; mi++)
        #pragma unroll
        for (int ni = 0; ni < 4; ni++) {
            int col = wn * 32 + ni * 8 + tg * 2;
            #pragma unroll
            for (int hh = 0; hh < 2; hh++) {
                int r = wm * 64 + mi * 16 + g + hh * 8;
                Csm[r * 132 + col]     = acc[mi][ni][2 * hh];
                Csm[r * 132 + col + 1] = acc[mi][ni][2 * hh + 1];
            }
        }
    __syncthreads();

    // ---- RoPE + fp16 store: thread -> one 64-col head chunk of one row ----
    {
        int r = tid >> 1;                 // 0..127
        int chunk = (tid & 1) * 64;       // 0 or 64
        int m = m0 + r;
        int gc0 = n0 + chunk;             // global col base of this head-chunk
        __half* dst = Oq + (long long)m * QKVN + gc0;
        const float* src = Csm + r * 132 + chunk;
        if (gc0 < 1280) {                 // q or k head: rotate
            int pos = m & (S_ - 1);
            #pragma unroll
            for (int d = 0; d < 32; d++) {
                float x1 = src[d], x2 = src[d + 32];
                float freq = expf(-logf(1.0e6f) * (2.0f * d) / 64.0f);
                float sn, cs;
                sincosf((float)pos * freq, &sn, &cs);
                dst[d]      = __float2half_rn(x1 * cs - x2 * sn);
                dst[d + 32] = __float2half_rn(x2 * cs + x1 * sn);
            }
        } else {                          // v: passthrough
            #pragma unroll
            for (int d = 0; d < 64; d += 2)
                *(__half2*)&dst[d] = __floats2half2_rn(src[d], src[d + 1]);
        }
    }
}

// ---------------- dense fp16 GEMM (WO) ----------------
__global__ __launch_bounds__(256, 2)
void gemm_h_kernel(const __half* __restrict__ A, const __half* __restrict__ W,
                   float* __restrict__ Cf, const float* __restrict__ resid,
                   int M, int N, int K) {
    int m0 = blockIdx.y * GBM;
    if (m0 >= M) return;
    int n0 = blockIdx.x * GBN;

    extern __shared__ __half hsmem[];
    const uint32_t smem_b = (uint32_t)__cvta_generic_to_shared(hsmem);

    const int tid = threadIdx.x;
    const int lane = tid & 31;
    const int warp = tid >> 5;
    const int wm = warp >> 2;
    const int wn = warp & 3;

    const int ar = tid >> 1;
    const int ac4 = (tid & 1) * 4;
    const __half* aptr = A + (long long)(m0 + ar) * K + ac4 * 8;
    const int br = tid >> 4, bc16 = tid & 15;
    const __half* b_base = W + n0 + bc16 * 8;

    const int nk = K / HGBK;

    auto prefetch = [&](int ki, int s) {
        uint32_t st = smem_b + s * HSTAGE * 2;
        int k0 = ki * HGBK;
        uint32_t dA = st + (ar * HASTRIDE + ac4 * 8) * 2;
        #pragma unroll
        for (int j = 0; j < 4; j++)
            cp16(dA + j * 16, aptr + k0 + j * 8, 16);
        uint32_t dB = st + (HA_PLANE + br * BSTRIDE + bc16 * 8) * 2;
        #pragma unroll
        for (int j = 0; j < 4; j++)
            cp16(dB + j * 16 * BSTRIDE * 2, b_base + (long long)(k0 + br + j * 16) * N, 16);
        asm volatile("cp.async.commit_group;");
    };

    float acc[4][4][4];
    #pragma unroll
    for (int mi = 0; mi < 4; mi++)
        #pragma unroll
        for (int ni = 0; ni < 4; ni++)
            #pragma unroll
            for (int r = 0; r < 4; r++) acc[mi][ni][r] = 0.f;

    prefetch(0, 0);

    for (int i = 0; i < nk; i++) {
        if (i + 1 < nk) {
            prefetch(i + 1, (i + 1) & 1);
            asm volatile("cp.async.wait_group 1;");
        } else {
            asm volatile("cp.async.wait_group 0;");
        }
        __syncthreads();

        uint32_t st = smem_b + (i & 1) * HSTAGE * 2;
        mma_step64(st, st + HA_PLANE * 2, 0,  wm, wn, lane, acc);
        mma_step64(st, st + HA_PLANE * 2, 16, wm, wn, lane, acc);
        mma_step64(st, st + HA_PLANE * 2, 32, wm, wn, lane, acc);
        mma_step64(st, st + HA_PLANE * 2, 48, wm, wn, lane, acc);
        __syncthreads();
    }

    const int g = lane >> 2, tg = lane & 3;
    #pragma unroll
    for (int mi = 0; mi < 4; mi++)
        #pragma unroll
        for (int ni = 0; ni < 4; ni++) {
            int col = n0 + wn * 32 + ni * 8 + tg * 2;
            #pragma unroll
            for (int hh = 0; hh < 2; hh++) {
                int m = m0 + wm * 64 + mi * 16 + g + hh * 8;
                float v0 = acc[mi][ni][2 * hh], v1 = acc[mi][ni][2 * hh + 1];
                if (resid) {
                    v0 += resid[(long long)m * N + col];
                    v1 += resid[(long long)m * N + col + 1];
                }
                *(float2*)&Cf[(long long)m * N + col] = make_float2(v0, v1);
            }
        }
}

// ---- helpers for fp32-B loaders ----
__device__ __forceinline__ void sts_half8(uint32_t dst, float4 v0, float4 v1) {
    __half2 q0 = __floats2half2_rn(v0.x, v0.y);
    __half2 q1 = __floats2half2_rn(v0.z, v0.w);
    __half2 q2 = __floats2half2_rn(v1.x, v1.y);
    __half2 q3 = __floats2half2_rn(v1.z, v1.w);
    asm volatile("st.shared.v4.b32 [%0], {%1, %2, %3, %4};"
                 :: "r"(dst), "r"(*(uint32_t*)&q0), "r"(*(uint32_t*)&q1),
                    "r"(*(uint32_t*)&q2), "r"(*(uint32_t*)&q3));
}

// ---------------- fused MoE gate+up GEMM, B read as fp32 -------------------
__global__ __launch_bounds__(256, 2)
void gemm_gu32_kernel(const __half* __restrict__ A,
                      const float* __restrict__ Wg, const float* __restrict__ Wu,
                      __half* __restrict__ Act,
                      int N, int K,
                      const int* __restrict__ cnt,
                      const int* __restrict__ gather,
                      const int* __restrict__ pairmap,
                      long long wstride) {
    int e = blockIdx.z;
    int M = cnt[e];
    Wg += (long long)e * wstride;
    Wu += (long long)e * wstride;
    gather += e * T_;
    pairmap += e * T_;
    int m0 = blockIdx.y * GBM;
    if (m0 >= M) return;
    int n0 = blockIdx.x * 64;

    extern __shared__ __half hsmem[];
    const uint32_t smem_b = (uint32_t)__cvta_generic_to_shared(hsmem);

    const int tid = threadIdx.x;
    const int lane = tid & 31;
    const int warp = tid >> 5;
    const int wm = warp >> 2;
    const int wn = warp & 3;

    const int ar = tid >> 1;
    const int ac4 = (tid & 1) * 4;
    int arow = -1;
    {
        int r = m0 + ar;
        if (r < M) arow = gather[r];
    }
    const __half* aptr = A + (arow < 0 ? 0 : (long long)arow * K) + ac4 * 8;
    const int au = arow < 0 ? 0 : 16;
    const int br = tid >> 4, bc16 = tid & 15;
    const float* b_base = (bc16 < 8 ? Wg + n0 + bc16 * 8 : Wu + n0 + (bc16 - 8) * 8);

    const int nk = K / HGBK;

    auto prefA = [&](int ki, int s) {
        uint32_t st = smem_b + s * HSTAGE * 2;
        int k0 = ki * HGBK;
        uint32_t dA = st + (ar * HASTRIDE + ac4 * 8) * 2;
        #pragma unroll
        for (int j = 0; j < 4; j++)
            cp16(dA + j * 16, aptr + k0 + j * 8, au);
        asm volatile("cp.async.commit_group;");
    };
    auto ldgB = [&](int ki, int j, float4& v0, float4& v1) {
        const float* p = b_base + (long long)(ki * HGBK + br + j * 16) * N;
        v0 = *(const float4*)p;
        v1 = *(const float4*)(p + 4);
    };
    auto stsB = [&](int s, int j, float4 v0, float4 v1) {
        uint32_t dst = smem_b + s * HSTAGE * 2
                     + (HA_PLANE + (br + j * 16) * BSTRIDE + bc16 * 8) * 2;
        sts_half8(dst, v0, v1);
    };

    float acc[4][4][4];
    #pragma unroll
    for (int mi = 0; mi < 4; mi++)
        #pragma unroll
        for (int ni = 0; ni < 4; ni++)
            #pragma unroll
            for (int r = 0; r < 4; r++) acc[mi][ni][r] = 0.f;

    prefA(0, 0);
    #pragma unroll
    for (int j = 0; j < 4; j++) {
        float4 v0, v1;
        ldgB(0, j, v0, v1);
        stsB(0, j, v0, v1);
    }
    asm volatile("cp.async.wait_group 0;");
    __syncthreads();

    for (int i = 0; i < nk; i++) {
        uint32_t st = smem_b + (i & 1) * HSTAGE * 2;
        const uint32_t sA = st, sB = st + HA_PLANE * 2;
        const int nxt = (i + 1) & 1;
        const bool more = (i + 1 < nk);
        float4 v0a, v1a, v0b, v1b;
        if (more) {
            prefA(i + 1, nxt);
            ldgB(i + 1, 0, v0a, v1a);
            ldgB(i + 1, 1, v0b, v1b);
        }
        mma_step64(sA, sB, 0,  wm, wn, lane, acc);
        mma_step64(sA, sB, 16, wm, wn, lane, acc);
        if (more) {
            stsB(nxt, 0, v0a, v1a);
            stsB(nxt, 1, v0b, v1b);
            ldgB(i + 1, 2, v0a, v1a);
            ldgB(i + 1, 3, v0b, v1b);
        }
        mma_step64(sA, sB, 32, wm, wn, lane, acc);
        mma_step64(sA, sB, 48, wm, wn, lane, acc);
        if (more) {
            stsB(nxt, 2, v0a, v1a);
            stsB(nxt, 3, v0b, v1b);
            asm volatile("cp.async.wait_group 0;");
        }
        __syncthreads();
    }

    float* Csm = (float*)hsmem;
    const int g = lane >> 2, tg = lane & 3;
    #pragma unroll
    for (int mi = 0; mi < 4; mi++)
        #pragma unroll
        for (int ni = 0; ni < 4; ni++) {
            int col = wn * 32 + ni * 8 + tg * 2;
            #pragma unroll
            for (int hh = 0; hh < 2; hh++) {
                int r = wm * 64 + mi * 16 + g + hh * 8;
                Csm[r * 130 + col]     = acc[mi][ni][2 * hh];
                Csm[r * 130 + col + 1] = acc[mi][ni][2 * hh + 1];
            }
        }
    __syncthreads();

    {
        int r = tid >> 1;
        int cb = (tid & 1) * 32;
        int m = m0 + r;
        if (m < M) {
            int cr = pairmap[m];
            long long idx = (long long)cr * N + n0 + cb;
            #pragma unroll
            for (int j = 0; j < 32; j += 2) {
                float g0 = Csm[r * 130 + cb + j];
                float g1 = Csm[r * 130 + cb + j + 1];
                float u0 = Csm[r * 130 + 64 + cb + j];
                float u1 = Csm[r * 130 + 64 + cb + j + 1];
                float a0 = g0 / (1.f + __expf(-g0)) * u0;
                float a1 = g1 / (1.f + __expf(-g1)) * u1;
                *(__half2*)&Act[idx + j] = __floats2half2_rn(a0, a1);
            }
        }
    }
}

// ---------------- MoE down GEMM, B read as fp32, fp32 scatter --------------
__global__ __launch_bounds__(256, 2)
void gemm_d32_kernel(const __half* __restrict__ A, const float* __restrict__ Wd,
                     float* __restrict__ Cf,
                     int N, int K,
                     const int* __restrict__ cnt,
                     const int* __restrict__ gather,
                     const int* __restrict__ pairmap,
                     long long wstride) {
    int e = blockIdx.z;
    int M = cnt[e];
    Wd += (long long)e * wstride;
    gather += e * T_;
    pairmap += e * T_;
    int m0 = blockIdx.y * GBM;
    if (m0 >= M) return;
    int n0 = blockIdx.x * GBN;

    extern __shared__ __half hsmem[];
    const uint32_t smem_b = (uint32_t)__cvta_generic_to_shared(hsmem);

    const int tid = threadIdx.x;
    const int lane = tid & 31;
    const int warp = tid >> 5;
    const int wm = warp >> 2;
    const int wn = warp & 3;

    const int ar = tid >> 1;
    const int ac4 = (tid & 1) * 4;
    int arow = -1;
    {
        int r = m0 + ar;
        if (r < M) arow = gather[r];
    }
    const __half* aptr = A + (arow < 0 ? 0 : (long long)arow * K) + ac4 * 8;
    const int au = arow < 0 ? 0 : 16;
    const int br = tid >> 4, bc16 = tid & 15;
    const float* b_base = Wd + n0 + bc16 * 8;

    const int nk = K / HGBK;

    auto prefA = [&](int ki, int s) {
        uint32_t st = smem_b + s * HSTAGE * 2;
        int k0 = ki * HGBK;
        uint32_t dA = st + (ar * HASTRIDE + ac4 * 8) * 2;
        #pragma unroll
        for (int j = 0; j < 4; j++)
            cp16(dA + j * 16, aptr + k0 + j * 8, au);
        asm volatile("cp.async.commit_group;");
    };
    auto ldgB = [&](int ki, int j, float4& v0, float4& v1) {
        const float* p = b_base + (long long)(ki * HGBK + br + j * 16) * N;
        v0 = *(const float4*)p;
        v1 = *(const float4*)(p + 4);
    };
    auto stsB = [&](int s, int j, float4 v0, float4 v1) {
        uint32_t dst = smem_b + s * HSTAGE * 2
                     + (HA_PLANE + (br + j * 16) * BSTRIDE + bc16 * 8) * 2;
        sts_half8(dst, v0, v1);
    };

    float acc[4][4][4];
    #pragma unroll
    for (int mi = 0; mi < 4; mi++)
        #pragma unroll
        for (int ni = 0; ni < 4; ni++)
            #pragma unroll
            for (int r = 0; r < 4; r++) acc[mi][ni][r] = 0.f;

    prefA(0, 0);
    #pragma unroll
    for (int j = 0; j < 4; j++) {
        float4 v0, v1;
        ldgB(0, j, v0, v1);
        stsB(0, j, v0, v1);
    }
    asm volatile("cp.async.wait_group 0;");
    __syncthreads();

    for (int i = 0; i < nk; i++) {
        uint32_t st = smem_b + (i & 1) * HSTAGE * 2;
        const uint32_t sA = st, sB = st + HA_PLANE * 2;
        const int nxt = (i + 1) & 1;
        const bool more = (i + 1 < nk);
        float4 v0a, v1a, v0b, v1b;
        if (more) {
            prefA(i + 1, nxt);
            ldgB(i + 1, 0, v0a, v1a);
            ldgB(i + 1, 1, v0b, v1b);
        }
        mma_step64(sA, sB, 0,  wm, wn, lane, acc);
        mma_step64(sA, sB, 16, wm, wn, lane, acc);
        if (more) {
            stsB(nxt, 0, v0a, v1a);
            stsB(nxt, 1, v0b, v1b);
            ldgB(i + 1, 2, v0a, v1a);
            ldgB(i + 1, 3, v0b, v1b);
        }
        mma_step64(sA, sB, 32, wm, wn, lane, acc);
        mma_step64(sA, sB, 48, wm, wn, lane, acc);
        if (more) {
            stsB(nxt, 2, v0a, v1a);
            stsB(nxt, 3, v0b, v1b);
            asm volatile("cp.async.wait_group 0;");
        }
        __syncthreads();
    }

    const int g = lane >> 2, tg = lane & 3;
    #pragma unroll
    for (int mi = 0; mi < 4; mi++)
        #pragma unroll
        for (int ni = 0; ni < 4; ni++) {
            int mloc = wm * 64 + mi * 16 + g;
            int col = n0 + wn * 32 + ni * 8 + tg * 2;
            #pragma unroll
            for (int hh = 0; hh < 2; hh++) {
                int m = m0 + mloc + hh * 8;
                if (m >= M) continue;
                int cr = pairmap[m];
                *(float2*)&Cf[(long long)cr * N + col] =
                    make_float2(acc[mi][ni][2 * hh], acc[mi][ni][2 * hh + 1]);
            }
        }
}

// ---------------- fp16 flash attention, double-buffered K/V ----------------
#define ATSTR 72
#define AQ 0
#define AKV0 4608
#define AKVSZ 9216
#define ASMEM ((AKV0 + 2 * AKVSZ) * 2)

__global__ __launch_bounds__(128)
void attn_tc_kernel(const __half* __restrict__ QKV16, __half* __restrict__ O16) {
    const int qt = blockIdx.x, bh = blockIdx.y;
    const int b = bh >> 4, h = bh & 15;
    const int kvh = h >> 2;
    const int q0 = qt * 64;
    const int tid = threadIdx.x, lane = tid & 31, w = tid >> 5;
    const int g = lane >> 2, tg = lane & 3;

    extern __shared__ __half asmem[];
    const uint32_t smb = (uint32_t)__cvta_generic_to_shared(asmem);

    auto prefetch_kv = [&](int kc, int buf) {
        const int k0 = kc * 64;
        #pragma unroll
        for (int t2 = 0; t2 < 2; t2++) {
            const __half* src = QKV16 + (t2 == 0 ? 1024 : 1280) + kvh * 64;
            #pragma unroll
            for (int ii = 0; ii < 4; ii++) {
                int rem = tid + ii * 128;
                int row = rem >> 3, c = rem & 7;
                uint32_t dst = smb + (AKV0 + buf * AKVSZ + t2 * 4608 + row * ATSTR + c * 8) * 2;
                cp16(dst, src + (long long)(b * S_ + k0 + row) * QKVN + c * 8, 16);
            }
        }
        asm volatile("cp.async.commit_group;");
    };

    {
        #pragma unroll
        for (int ii = 0; ii < 4; ii++) {
            int rem = tid + ii * 128;
            int row = rem >> 3, c = rem & 7;
            uint32_t dst = smb + (AQ + row * ATSTR + c * 8) * 2;
            cp16(dst, QKV16 + (long long)(b * S_ + q0 + row) * QKVN + h * 64 + c * 8, 16);
        }
        asm volatile("cp.async.commit_group;");
    }
    prefetch_kv(0, 0);
    asm volatile("cp.async.wait_group 1;");
    __syncthreads();

    uint32_t qf[4][4];
    #pragma unroll
    for (int kk = 0; kk < 4; kk++) {
        uint32_t off = ((w * 16 + (lane & 15)) * ATSTR + kk * 16 + (lane >> 4) * 8) * 2;
        asm volatile("ldmatrix.sync.aligned.m8n8.x4.shared.b16 {%0,%1,%2,%3}, [%4];"
                     : "=r"(qf[kk][0]), "=r"(qf[kk][1]), "=r"(qf[kk][2]), "=r"(qf[kk][3])
                     : "r"(smb + AQ * 2 + off));
    }

    float o[8][4];
    #pragma unroll
    for (int n = 0; n < 8; n++)
        #pragma unroll
        for (int r = 0; r < 4; r++) o[n][r] = 0.f;
    float m0 = -INFINITY, m1 = -INFINITY, l0 = 0.f, l1 = 0.f;

    for (int kc = 0; kc <= qt; kc++) {
        asm volatile("cp.async.wait_group 0;");
        __syncthreads();
        if (kc < qt) prefetch_kv(kc + 1, (kc + 1) & 1);

        const uint32_t sK = smb + (AKV0 + (kc & 1) * AKVSZ) * 2;
        const uint32_t sV = sK + 4608 * 2;

        float sf[8][4];
        #pragma unroll
        for (int n = 0; n < 8; n++)
            #pragma unroll
            for (int r = 0; r < 4; r++) sf[n][r] = 0.f;

        #pragma unroll
        for (int kk = 0; kk < 4; kk++) {
            #pragma unroll
            for (int np = 0; np < 4; np++) {
                uint32_t off = ((np * 16 + (lane & 7) + ((lane >> 4) << 3)) * ATSTR
                                + kk * 16 + ((lane >> 3) & 1) * 8) * 2;
                uint32_t kf[4];
                asm volatile("ldmatrix.sync.aligned.m8n8.x4.shared.b16 {%0,%1,%2,%3}, [%4];"
                             : "=r"(kf[0]), "=r"(kf[1]), "=r"(kf[2]), "=r"(kf[3])
                             : "r"(sK + off));
                MMAH16816(sf[2 * np],     qf[kk], kf);
                MMAH16816(sf[2 * np + 1], qf[kk], kf + 2);
            }
        }

        const float sc = 0.125f;
        if (kc == qt) {
            int r0loc = w * 16 + g, r1loc = r0loc + 8;
            #pragma unroll
            for (int n = 0; n < 8; n++) {
                int c0 = 8 * n + 2 * tg, c1 = c0 + 1;
                sf[n][0] = (c0 <= r0loc) ? sf[n][0] * sc : -INFINITY;
                sf[n][1] = (c1 <= r0loc) ? sf[n][1] * sc : -INFINITY;
                sf[n][2] = (c0 <= r1loc) ? sf[n][2] * sc : -INFINITY;
                sf[n][3] = (c1 <= r1loc) ? sf[n][3] * sc : -INFINITY;
            }
        } else {
            #pragma unroll
            for (int n = 0; n < 8; n++)
                #pragma unroll
                for (int r = 0; r < 4; r++) sf[n][r] *= sc;
        }

        float mx0 = -INFINITY, mx1 = -INFINITY;
        #pragma unroll
        for (int n = 0; n < 8; n++) {
            mx0 = fmaxf(mx0, fmaxf(sf[n][0], sf[n][1]));
            mx1 = fmaxf(mx1, fmaxf(sf[n][2], sf[n][3]));
        }
        mx0 = fmaxf(mx0, __shfl_xor_sync(~0u, mx0, 1));
        mx0 = fmaxf(mx0, __shfl_xor_sync(~0u, mx0, 2));
        mx1 = fmaxf(mx1, __shfl_xor_sync(~0u, mx1, 1));
        mx1 = fmaxf(mx1, __shfl_xor_sync(~0u, mx1, 2));
        float nm0 = fmaxf(m0, mx0), nm1 = fmaxf(m1, mx1);
        float f0 = __expf(m0 - nm0), f1 = __expf(m1 - nm1);
        m0 = nm0; m1 = nm1;
        float s0 = 0.f, s1 = 0.f;
        #pragma unroll
        for (int n = 0; n < 8; n++) {
            float p;
            p = __expf(sf[n][0] - nm0); sf[n][0] = p; s0 += p;
            p = __expf(sf[n][1] - nm0); sf[n][1] = p; s0 += p;
            p = __expf(sf[n][2] - nm1); sf[n][2] = p; s1 += p;
            p = __expf(sf[n][3] - nm1); sf[n][3] = p; s1 += p;
        }
        s0 += __shfl_xor_sync(~0u, s0, 1); s0 += __shfl_xor_sync(~0u, s0, 2);
        s1 += __shfl_xor_sync(~0u, s1, 1); s1 += __shfl_xor_sync(~0u, s1, 2);
        l0 = l0 * f0 + s0;
        l1 = l1 * f1 + s1;
        #pragma unroll
        for (int n = 0; n < 8; n++) {
            o[n][0] *= f0; o[n][1] *= f0; o[n][2] *= f1; o[n][3] *= f1;
        }

        #pragma unroll
        for (int kk = 0; kk < 4; kk++) {
            uint32_t pa[4];
            {
                float* c0 = sf[2 * kk];
                float* c1 = sf[2 * kk + 1];
                __half2 p0 = __floats2half2_rn(c0[0], c0[1]);
                __half2 p1 = __floats2half2_rn(c0[2], c0[3]);
                __half2 p2 = __floats2half2_rn(c1[0], c1[1]);
                __half2 p3 = __floats2half2_rn(c1[2], c1[3]);
                pa[0] = *(uint32_t*)&p0;
                pa[1] = *(uint32_t*)&p1;
                pa[2] = *(uint32_t*)&p2;
                pa[3] = *(uint32_t*)&p3;
            }
            #pragma unroll
            for (int dp = 0; dp < 4; dp++) {
                uint32_t off = ((kk * 16 + (lane & 15)) * ATSTR + dp * 16 + (lane >> 4) * 8) * 2;
                uint32_t vf[4];
                asm volatile("ldmatrix.sync.aligned.m8n8.x4.trans.shared.b16 {%0,%1,%2,%3}, [%4];"
                             : "=r"(vf[0]), "=r"(vf[1]), "=r"(vf[2]), "=r"(vf[3])
                             : "r"(sV + off));
                MMAH16816(o[2 * dp],     pa, vf);
                MMAH16816(o[2 * dp + 1], pa, vf + 2);
            }
        }
    }

    float il0 = 1.f / l0, il1 = 1.f / l1;
    int row0 = q0 + w * 16 + g, row1 = row0 + 8;
    #pragma unroll
    for (int n = 0; n < 8; n++) {
        int col = 8 * n + 2 * tg;
        long long i0 = ((long long)(b * S_ + row0) * NH_ + h) * 64 + col;
        long long i1 = ((long long)(b * S_ + row1) * NH_ + h) * 64 + col;
        *(__half2*)&O16[i0] = __floats2half2_rn(o[n][0] * il0, o[n][1] * il0);
        *(__half2*)&O16[i1] = __floats2half2_rn(o[n][2] * il1, o[n][3] * il1);
    }
}

// ---------------- router ----------------
__global__ void reset_kernel(int* cnt) {
    if (threadIdx.x < E_) cnt[threadIdx.x] = 0;
}

__global__ void router_kernel(const float* __restrict__ Xn, const float* __restrict__ RW,
                              int* __restrict__ cnt, int* __restrict__ tok,
                              int* __restrict__ pairm, float* __restrict__ pairw) {
    int t = blockIdx.x * 4 + (threadIdx.x >> 5);
    int lane = threadIdx.x & 31;
    if (t >= T_) return;
    float acc[E_];
    #pragma unroll
    for (int e = 0; e < E_; e++) acc[e] = 0.f;
    const float* x = Xn + (long long)t * H_;
    for (int k = lane; k < H_; k += 32) {
        float xv = x[k];
        #pragma unroll
        for (int e = 0; e < E_; e++) acc[e] = fmaf(xv, RW[k * E_ + e], acc[e]);
    }
    #pragma unroll
    for (int e = 0; e < E_; e++)
        #pragma unroll
        for (int o = 16; o; o >>= 1) acc[e] += __shfl_xor_sync(~0u, acc[e], o);
    if (lane == 0) {
        float mx = acc[0];
        #pragma unroll
        for (int e = 1; e < E_; e++) mx = fmaxf(mx, acc[e]);
        float p[E_], s = 0.f;
        #pragma unroll
        for (int e = 0; e < E_; e++) { p[e] = expf(acc[e] - mx); s += p[e]; }
        #pragma unroll
        for (int e = 0; e < E_; e++) p[e] /= s;
        int i0 = 0; float v0 = p[0];
        #pragma unroll
        for (int e = 1; e < E_; e++) if (p[e] > v0) { v0 = p[e]; i0 = e; }
        int i1 = -1; float v1 = -1.f;
        #pragma unroll
        for (int e = 0; e < E_; e++) if (e != i0 && p[e] > v1) { v1 = p[e]; i1 = e; }
        if (i1 < 0) i1 = i0 ? 0 : 1;
        float tw = v0 + v1;
        pairw[t * 2]     = v0 / tw;
        pairw[t * 2 + 1] = v1 / tw;
        int r0 = atomicAdd(&cnt[i0], 1);
        tok[i0 * T_ + r0] = t; pairm[i0 * T_ + r0] = t * 2;
        int r1 = atomicAdd(&cnt[i1], 1);
        tok[i1 * T_ + r1] = t; pairm[i1 * T_ + r1] = t * 2 + 1;
    }
}

// ---------------- combine ----------------
__global__ void combine_kernel(const float* __restrict__ hidden, const float* __restrict__ down,
                               const float* __restrict__ pairw, float* __restrict__ out) {
    long long i = (long long)blockIdx.x * 256 + threadIdx.x;
    if (i >= (long long)T_ * H_) return;
    int t = (int)(i >> 10);
    int hh = (int)(i & 1023);
    out[i] = hidden[i]
           + pairw[t * 2]     * down[((long long)t * 2)     * H_ + hh]
           + pairw[t * 2 + 1] * down[((long long)t * 2 + 1) * H_ + hh];
}

// ---------------- launcher ----------------
extern "C" void kernel_launch(void* const* d_in, const int* in_sizes, int n_in,
                              void* d_out, int out_size) {
    const float* hs    = (const float*)d_in[0];
    const float* ln1   = (const float*)d_in[2];
    const float* ln2   = (const float*)d_in[3];
    const float* wq    = (const float*)d_in[4];
    const float* wk    = (const float*)d_in[5];
    const float* wv    = (const float*)d_in[6];
    const float* wo    = (const float*)d_in[7];
    const float* rw    = (const float*)d_in[8];
    const float* wgate = (const float*)d_in[9];
    const float* wup   = (const float*)d_in[10];
    const float* wdown = (const float*)d_in[11];
    float* out = (float*)d_out;

    float *phid, *pxn, *pdowno, *ppw;
    int *pcnt, *ptok, *ppm;
    __half *x16, *qkv16, *wqkv16, *at16, *wo16, *xn16, *act16;
    cudaGetSymbolAddress((void**)&phid,   g_hidden);
    cudaGetSymbolAddress((void**)&pxn,    g_xn);
    cudaGetSymbolAddress((void**)&pdowno, g_downo);
    cudaGetSymbolAddress((void**)&ppw,    g_pairw);
    cudaGetSymbolAddress((void**)&pcnt,   g_cnt);
    cudaGetSymbolAddress((void**)&ptok,   g_tok);
    cudaGetSymbolAddress((void**)&ppm,    g_pairm);
    cudaGetSymbolAddress((void**)&x16,   h_x);
    cudaGetSymbolAddress((void**)&qkv16, h_qkv);
    cudaGetSymbolAddress((void**)&wqkv16, h_wqkv);
    cudaGetSymbolAddress((void**)&at16, h_at);
    cudaGetSymbolAddress((void**)&wo16, h_wo);
    cudaGetSymbolAddress((void**)&xn16, h_xn);
    cudaGetSymbolAddress((void**)&act16, h_act);

    cudaFuncSetAttribute(gemm_qkv_kernel, cudaFuncAttributeMaxDynamicSharedMemorySize, HSMEM2);
    cudaFuncSetAttribute(gemm_h_kernel, cudaFuncAttributeMaxDynamicSharedMemorySize, HSMEM2);
    cudaFuncSetAttribute(gemm_gu32_kernel, cudaFuncAttributeMaxDynamicSharedMemorySize, HSMEM2);
    cudaFuncSetAttribute(gemm_d32_kernel, cudaFuncAttributeMaxDynamicSharedMemorySize, HSMEM2);
    cudaFuncSetAttribute(attn_tc_kernel, cudaFuncAttributeMaxDynamicSharedMemorySize, ASMEM);

    // ---- merged small weight conversion (qkv pack + wo), one launch ----
    long long nconv = (long long)NQW + 2 * NKW + NQW;
    convw_kernel<<<(int)((nconv / 4 + 255) / 256), 256>>>(wq, wk, wv, wo, wqkv16, wo16);

    // 1) ln1 -> fp16
    rmsnorm_kernel<<<T_, 256>>>(hs, ln1, nullptr, x16);
    // 2) QKV projection with fused RoPE + fp16 epilogue
    gemm_qkv_kernel<<<dim3(QKVN / GBN, T_ / GBM, 1), 256, HSMEM2>>>(
        x16, wqkv16, qkv16, T_, QKVN, H_);
    // 3) attention
    attn_tc_kernel<<<dim3(S_ / 64, B_ * NH_), 128, ASMEM>>>(qkv16, at16);
    // 4) out projection + residual
    gemm_h_kernel<<<dim3(H_ / GBN, T_ / GBM, 1), 256, HSMEM2>>>(
        at16, wo16, phid, hs, T_, H_, NH_ * HD_);
    // 5) ln2
    rmsnorm_kernel<<<T_, 256>>>(phid, ln2, pxn, xn16);
    // 6) router + grouping
    reset_kernel<<<1, 32>>>(pcnt);
    router_kernel<<<T_ / 4, 128>>>(pxn, rw, pcnt, ptok, ppm, ppw);
    // 7) MoE fused gate+up, B read as fp32
    gemm_gu32_kernel<<<dim3(I_ / 64, T_ / GBM, E_), 256, HSMEM2>>>(
        xn16, wgate, wup, act16, I_, H_, pcnt, ptok, ppm, (long long)H_ * I_);
    // 8) down projection, B read as fp32
    gemm_d32_kernel<<<dim3(H_ / GBN, T_ / GBM, E_), 256, HSMEM2>>>(
        act16, wdown, pdowno, H_, I_, pcnt, ppm, ppm, (long long)I_ * H_);
    // 9) combine
    combine_kernel<<<(T_ * H_ + 255) / 256, 256>>>(phid, pdowno, ppw, out);
}

// round 16
// speedup vs baseline: 1.0477x; 1.0477x over previous
#include <cuda_runtime.h>
#include <cuda_bf16.h>
#include <cuda_fp16.h>
#include <math.h>
#include <stdint.h>

// ---------------- problem constants ----------------
#define B_   2
#define S_   1024
#define H_   1024
#define NH_  16
#define NKV_ 4
#define HD_  64
#define E_   8
#define TOPK_ 2
#define I_   3584
#define T_   (B_ * S_)
#define EPS_ 1e-5f
#define QKVN 1536
#define NQW  (H_ * NH_ * HD_)
#define NKW  (H_ * NKV_ * HD_)

// ---------------- fp32 scratch ----------------
__device__ float g_qkv[T_ * QKVN];
__device__ float g_hidden[T_ * H_];
__device__ float g_xn[T_ * H_];
__device__ float g_downo[(long long)T_ * TOPK_ * H_];
__device__ int   g_cnt[E_];
__device__ int   g_tok[E_ * T_];
__device__ int   g_pairm[E_ * T_];
__device__ float g_pairw[T_ * TOPK_];

// ---------------- fp16 planes ----------------
__device__ __half h_x[T_ * H_];
__device__ __half h_qkv[T_ * QKVN];
__device__ __half h_wqkv[H_ * QKVN];
__device__ __half h_at[T_ * H_];
__device__ __half h_wo[NH_ * HD_ * H_];
__device__ __half h_xn[T_ * H_];
__device__ __half h_act[(long long)T_ * TOPK_ * I_];

// ---------------- merged small weight conversion (wq|wk|wv -> packed, wo) --
__global__ void convw_kernel(const float* __restrict__ wq, const float* __restrict__ wk,
                             const float* __restrict__ wv, const float* __restrict__ wo,
                             __half* __restrict__ dqkv, __half* __restrict__ dwo) {
    long long idx = ((long long)blockIdx.x * 256 + threadIdx.x) * 4;
    const long long n1 = NQW, n2 = n1 + NKW, n3 = n2 + NKW, n4 = n3 + NQW;
    if (idx >= n4) return;
    if (idx >= n3) {
        long long i = idx - n3;
        float4 v = *(const float4*)(wo + i);
        *(__half2*)(dwo + i)     = __floats2half2_rn(v.x, v.y);
        *(__half2*)(dwo + i + 2) = __floats2half2_rn(v.z, v.w);
        return;
    }
    const float* src;
    long long i;
    int ncols, doff;
    if (idx < n1)      { src = wq; i = idx;      ncols = 1024; doff = 0; }
    else if (idx < n2) { src = wk; i = idx - n1; ncols = 256;  doff = 1024; }
    else               { src = wv; i = idx - n2; ncols = 256;  doff = 1280; }
    int row = (int)(i / ncols), col = (int)(i % ncols);
    float4 v = *(const float4*)(src + i);
    long long d = (long long)row * QKVN + doff + col;
    *(__half2*)(dqkv + d)     = __floats2half2_rn(v.x, v.y);
    *(__half2*)(dqkv + d + 2) = __floats2half2_rn(v.z, v.w);
}

// ---------------- RMSNorm ----------------
__global__ void rmsnorm_kernel(const float* __restrict__ X, const float* __restrict__ w,
                               float* __restrict__ Yf, __half* __restrict__ Y16) {
    int t = blockIdx.x;
    const float* x = X + (long long)t * H_;
    float ss = 0.f;
    for (int i = threadIdx.x; i < H_; i += 256) { float v = x[i]; ss = fmaf(v, v, ss); }
    #pragma unroll
    for (int o = 16; o; o >>= 1) ss += __shfl_xor_sync(~0u, ss, o);
    __shared__ float red[8];
    __shared__ float rs;
    if ((threadIdx.x & 31) == 0) red[threadIdx.x >> 5] = ss;
    __syncthreads();
    if (threadIdx.x == 0) {
        float s = 0.f;
        #pragma unroll
        for (int i = 0; i < 8; i++) s += red[i];
        rs = rsqrtf(s / (float)H_ + EPS_);
    }
    __syncthreads();
    float r = rs;
    for (int i = threadIdx.x; i < H_; i += 256) {
        float y = x[i] * r * w[i];
        if (Yf) Yf[(long long)t * H_ + i] = y;
        Y16[(long long)t * H_ + i] = __float2half_rn(y);
    }
}

// ---------------- tile constants ----------------
#define GBM 128
#define GBN 128
#define BSTRIDE 136
#define HGBK 64
#define HASTRIDE 72
#define HA_PLANE (GBM * HASTRIDE)
#define HB_PLANE (HGBK * BSTRIDE)
#define HSTAGE (HA_PLANE + HB_PLANE)
#define HSMEM2 (2 * HSTAGE * 2)

#define MMAH16816(d, a, b)                                                      \
    asm volatile("mma.sync.aligned.m16n8k16.row.col.f32.f16.f16.f32 "           \
                 "{%0,%1,%2,%3}, {%4,%5,%6,%7}, {%8,%9}, {%0,%1,%2,%3};"        \
                 : "+f"((d)[0]), "+f"((d)[1]), "+f"((d)[2]), "+f"((d)[3])       \
                 : "r"((a)[0]), "r"((a)[1]), "r"((a)[2]), "r"((a)[3]),          \
                   "r"((b)[0]), "r"((b)[1]))

__device__ __forceinline__ void cp16(uint32_t dst, const void* src, int use) {
    asm volatile("cp.async.cg.shared.global [%0], [%1], 16, %2;"
                 :: "r"(dst), "l"(src), "r"(use));
}

// one ks16-step of the 128x128 warp-tiled HMMA
__device__ __forceinline__ void mma_step64(uint32_t sA, uint32_t sB, int ks,
                                           int wm, int wn, int lane,
                                           float (*acc)[4][4]) {
    uint32_t af[4][4], bf[4][2];
    #pragma unroll
    for (int mi = 0; mi < 4; mi++) {
        uint32_t off = ((wm * 64 + mi * 16 + (lane & 15)) * HASTRIDE + ks + (lane >> 4) * 8) * 2;
        asm volatile("ldmatrix.sync.aligned.m8n8.x4.shared.b16 {%0,%1,%2,%3}, [%4];"
                     : "=r"(af[mi][0]), "=r"(af[mi][1]), "=r"(af[mi][2]), "=r"(af[mi][3])
                     : "r"(sA + off));
    }
    #pragma unroll
    for (int pp = 0; pp < 2; pp++) {
        uint32_t off = ((ks + (lane & 15)) * BSTRIDE + wn * 32 + pp * 16 + (lane >> 4) * 8) * 2;
        asm volatile("ldmatrix.sync.aligned.m8n8.x4.trans.shared.b16 {%0,%1,%2,%3}, [%4];"
                     : "=r"(bf[2 * pp][0]), "=r"(bf[2 * pp][1]),
                       "=r"(bf[2 * pp + 1][0]), "=r"(bf[2 * pp + 1][1])
                     : "r"(sB + off));
    }
    #pragma unroll
    for (int mi = 0; mi < 4; mi++)
        #pragma unroll
        for (int ni = 0; ni < 4; ni++)
            MMAH16816(acc[mi][ni], af[mi], bf[ni]);
}

// ---------------- dense fp16 GEMM (QKV / WO) ----------------
__global__ __launch_bounds__(256, 2)
void gemm_h_kernel(const __half* __restrict__ A, const __half* __restrict__ W,
                   float* __restrict__ Cf, const float* __restrict__ resid,
                   int M, int N, int K) {
    int m0 = blockIdx.y * GBM;
    if (m0 >= M) return;
    int n0 = blockIdx.x * GBN;

    extern __shared__ __half hsmem[];
    const uint32_t smem_b = (uint32_t)__cvta_generic_to_shared(hsmem);

    const int tid = threadIdx.x;
    const int lane = tid & 31;
    const int warp = tid >> 5;
    const int wm = warp >> 2;
    const int wn = warp & 3;

    const int ar = tid >> 1;
    const int ac4 = (tid & 1) * 4;
    const __half* aptr = A + (long long)(m0 + ar) * K + ac4 * 8;
    const int br = tid >> 4, bc16 = tid & 15;
    const __half* b_base = W + n0 + bc16 * 8;

    const int nk = K / HGBK;

    auto prefetch = [&](int ki, int s) {
        uint32_t st = smem_b + s * HSTAGE * 2;
        int k0 = ki * HGBK;
        uint32_t dA = st + (ar * HASTRIDE + ac4 * 8) * 2;
        #pragma unroll
        for (int j = 0; j < 4; j++)
            cp16(dA + j * 16, aptr + k0 + j * 8, 16);
        uint32_t dB = st + (HA_PLANE + br * BSTRIDE + bc16 * 8) * 2;
        #pragma unroll
        for (int j = 0; j < 4; j++)
            cp16(dB + j * 16 * BSTRIDE * 2, b_base + (long long)(k0 + br + j * 16) * N, 16);
        asm volatile("cp.async.commit_group;");
    };

    float acc[4][4][4];
    #pragma unroll
    for (int mi = 0; mi < 4; mi++)
        #pragma unroll
        for (int ni = 0; ni < 4; ni++)
            #pragma unroll
            for (int r = 0; r < 4; r++) acc[mi][ni][r] = 0.f;

    prefetch(0, 0);

    for (int i = 0; i < nk; i++) {
        if (i + 1 < nk) {
            prefetch(i + 1, (i + 1) & 1);
            asm volatile("cp.async.wait_group 1;");
        } else {
            asm volatile("cp.async.wait_group 0;");
        }
        __syncthreads();

        uint32_t st = smem_b + (i & 1) * HSTAGE * 2;
        mma_step64(st, st + HA_PLANE * 2, 0,  wm, wn, lane, acc);
        mma_step64(st, st + HA_PLANE * 2, 16, wm, wn, lane, acc);
        mma_step64(st, st + HA_PLANE * 2, 32, wm, wn, lane, acc);
        mma_step64(st, st + HA_PLANE * 2, 48, wm, wn, lane, acc);
        __syncthreads();
    }

    const int g = lane >> 2, tg = lane & 3;
    #pragma unroll
    for (int mi = 0; mi < 4; mi++)
        #pragma unroll
        for (int ni = 0; ni < 4; ni++) {
            int col = n0 + wn * 32 + ni * 8 + tg * 2;
            #pragma unroll
            for (int hh = 0; hh < 2; hh++) {
                int m = m0 + wm * 64 + mi * 16 + g + hh * 8;
                float v0 = acc[mi][ni][2 * hh], v1 = acc[mi][ni][2 * hh + 1];
                if (resid) {
                    v0 += resid[(long long)m * N + col];
                    v1 += resid[(long long)m * N + col + 1];
                }
                *(float2*)&Cf[(long long)m * N + col] = make_float2(v0, v1);
            }
        }
}

// ---- helpers for fp32-B loaders ----
__device__ __forceinline__ void sts_half8(uint32_t dst, float4 v0, float4 v1) {
    __half2 q0 = __floats2half2_rn(v0.x, v0.y);
    __half2 q1 = __floats2half2_rn(v0.z, v0.w);
    __half2 q2 = __floats2half2_rn(v1.x, v1.y);
    __half2 q3 = __floats2half2_rn(v1.z, v1.w);
    asm volatile("st.shared.v4.b32 [%0], {%1, %2, %3, %4};"
                 :: "r"(dst), "r"(*(uint32_t*)&q0), "r"(*(uint32_t*)&q1),
                    "r"(*(uint32_t*)&q2), "r"(*(uint32_t*)&q3));
}

// ---------------- fused MoE gate+up GEMM, B read as fp32 -------------------
__global__ __launch_bounds__(256, 2)
void gemm_gu32_kernel(const __half* __restrict__ A,
                      const float* __restrict__ Wg, const float* __restrict__ Wu,
                      __half* __restrict__ Act,
                      int N, int K,
                      const int* __restrict__ cnt,
                      const int* __restrict__ gather,
                      const int* __restrict__ pairmap,
                      long long wstride) {
    int e = blockIdx.z;
    int M = cnt[e];
    Wg += (long long)e * wstride;
    Wu += (long long)e * wstride;
    gather += e * T_;
    pairmap += e * T_;
    int m0 = blockIdx.y * GBM;
    if (m0 >= M) return;
    int n0 = blockIdx.x * 64;

    extern __shared__ __half hsmem[];
    const uint32_t smem_b = (uint32_t)__cvta_generic_to_shared(hsmem);

    const int tid = threadIdx.x;
    const int lane = tid & 31;
    const int warp = tid >> 5;
    const int wm = warp >> 2;
    const int wn = warp & 3;

    const int ar = tid >> 1;
    const int ac4 = (tid & 1) * 4;
    int arow = -1;
    {
        int r = m0 + ar;
        if (r < M) arow = gather[r];
    }
    const __half* aptr = A + (arow < 0 ? 0 : (long long)arow * K) + ac4 * 8;
    const int au = arow < 0 ? 0 : 16;
    const int br = tid >> 4, bc16 = tid & 15;
    const float* b_base = (bc16 < 8 ? Wg + n0 + bc16 * 8 : Wu + n0 + (bc16 - 8) * 8);

    const int nk = K / HGBK;

    auto prefA = [&](int ki, int s) {
        uint32_t st = smem_b + s * HSTAGE * 2;
        int k0 = ki * HGBK;
        uint32_t dA = st + (ar * HASTRIDE + ac4 * 8) * 2;
        #pragma unroll
        for (int j = 0; j < 4; j++)
            cp16(dA + j * 16, aptr + k0 + j * 8, au);
        asm volatile("cp.async.commit_group;");
    };
    auto ldgB = [&](int ki, int j, float4& v0, float4& v1) {
        const float* p = b_base + (long long)(ki * HGBK + br + j * 16) * N;
        v0 = *(const float4*)p;
        v1 = *(const float4*)(p + 4);
    };
    auto stsB = [&](int s, int j, float4 v0, float4 v1) {
        uint32_t dst = smem_b + s * HSTAGE * 2
                     + (HA_PLANE + (br + j * 16) * BSTRIDE + bc16 * 8) * 2;
        sts_half8(dst, v0, v1);
    };

    float acc[4][4][4];
    #pragma unroll
    for (int mi = 0; mi < 4; mi++)
        #pragma unroll
        for (int ni = 0; ni < 4; ni++)
            #pragma unroll
            for (int r = 0; r < 4; r++) acc[mi][ni][r] = 0.f;

    prefA(0, 0);
    #pragma unroll
    for (int j = 0; j < 4; j++) {
        float4 v0, v1;
        ldgB(0, j, v0, v1);
        stsB(0, j, v0, v1);
    }
    asm volatile("cp.async.wait_group 0;");
    __syncthreads();

    for (int i = 0; i < nk; i++) {
        uint32_t st = smem_b + (i & 1) * HSTAGE * 2;
        const uint32_t sA = st, sB = st + HA_PLANE * 2;
        const int nxt = (i + 1) & 1;
        const bool more = (i + 1 < nk);
        float4 v0a, v1a, v0b, v1b;
        if (more) {
            prefA(i + 1, nxt);
            ldgB(i + 1, 0, v0a, v1a);
            ldgB(i + 1, 1, v0b, v1b);
        }
        mma_step64(sA, sB, 0,  wm, wn, lane, acc);
        mma_step64(sA, sB, 16, wm, wn, lane, acc);
        if (more) {
            stsB(nxt, 0, v0a, v1a);
            stsB(nxt, 1, v0b, v1b);
            ldgB(i + 1, 2, v0a, v1a);
            ldgB(i + 1, 3, v0b, v1b);
        }
        mma_step64(sA, sB, 32, wm, wn, lane, acc);
        mma_step64(sA, sB, 48, wm, wn, lane, acc);
        if (more) {
            stsB(nxt, 2, v0a, v1a);
            stsB(nxt, 3, v0b, v1b);
            asm volatile("cp.async.wait_group 0;");
        }
        __syncthreads();
    }

    float* Csm = (float*)hsmem;
    const int g = lane >> 2, tg = lane & 3;
    #pragma unroll
    for (int mi = 0; mi < 4; mi++)
        #pragma unroll
        for (int ni = 0; ni < 4; ni++) {
            int col = wn * 32 + ni * 8 + tg * 2;
            #pragma unroll
            for (int hh = 0; hh < 2; hh++) {
                int r = wm * 64 + mi * 16 + g + hh * 8;
                Csm[r * 130 + col]     = acc[mi][ni][2 * hh];
                Csm[r * 130 + col + 1] = acc[mi][ni][2 * hh + 1];
            }
        }
    __syncthreads();

    {
        int r = tid >> 1;
        int cb = (tid & 1) * 32;
        int m = m0 + r;
        if (m < M) {
            int cr = pairmap[m];
            long long idx = (long long)cr * N + n0 + cb;
            #pragma unroll
            for (int j = 0; j < 32; j += 2) {
                float g0 = Csm[r * 130 + cb + j];
                float g1 = Csm[r * 130 + cb + j + 1];
                float u0 = Csm[r * 130 + 64 + cb + j];
                float u1 = Csm[r * 130 + 64 + cb + j + 1];
                float a0 = g0 / (1.f + __expf(-g0)) * u0;
                float a1 = g1 / (1.f + __expf(-g1)) * u1;
                *(__half2*)&Act[idx + j] = __floats2half2_rn(a0, a1);
            }
        }
    }
}

// ---------------- MoE down GEMM, B read as fp32, fp32 scatter --------------
__global__ __launch_bounds__(256, 2)
void gemm_d32_kernel(const __half* __restrict__ A, const float* __restrict__ Wd,
                     float* __restrict__ Cf,
                     int N, int K,
                     const int* __restrict__ cnt,
                     const int* __restrict__ gather,
                     const int* __restrict__ pairmap,
                     long long wstride) {
    int e = blockIdx.z;
    int M = cnt[e];
    Wd += (long long)e * wstride;
    gather += e * T_;
    pairmap += e * T_;
    int m0 = blockIdx.y * GBM;
    if (m0 >= M) return;
    int n0 = blockIdx.x * GBN;

    extern __shared__ __half hsmem[];
    const uint32_t smem_b = (uint32_t)__cvta_generic_to_shared(hsmem);

    const int tid = threadIdx.x;
    const int lane = tid & 31;
    const int warp = tid >> 5;
    const int wm = warp >> 2;
    const int wn = warp & 3;

    const int ar = tid >> 1;
    const int ac4 = (tid & 1) * 4;
    int arow = -1;
    {
        int r = m0 + ar;
        if (r < M) arow = gather[r];
    }
    const __half* aptr = A + (arow < 0 ? 0 : (long long)arow * K) + ac4 * 8;
    const int au = arow < 0 ? 0 : 16;
    const int br = tid >> 4, bc16 = tid & 15;
    const float* b_base = Wd + n0 + bc16 * 8;

    const int nk = K / HGBK;

    auto prefA = [&](int ki, int s) {
        uint32_t st = smem_b + s * HSTAGE * 2;
        int k0 = ki * HGBK;
        uint32_t dA = st + (ar * HASTRIDE + ac4 * 8) * 2;
        #pragma unroll
        for (int j = 0; j < 4; j++)
            cp16(dA + j * 16, aptr + k0 + j * 8, au);
        asm volatile("cp.async.commit_group;");
    };
    auto ldgB = [&](int ki, int j, float4& v0, float4& v1) {
        const float* p = b_base + (long long)(ki * HGBK + br + j * 16) * N;
        v0 = *(const float4*)p;
        v1 = *(const float4*)(p + 4);
    };
    auto stsB = [&](int s, int j, float4 v0, float4 v1) {
        uint32_t dst = smem_b + s * HSTAGE * 2
                     + (HA_PLANE + (br + j * 16) * BSTRIDE + bc16 * 8) * 2;
        sts_half8(dst, v0, v1);
    };

    float acc[4][4][4];
    #pragma unroll
    for (int mi = 0; mi < 4; mi++)
        #pragma unroll
        for (int ni = 0; ni < 4; ni++)
            #pragma unroll
            for (int r = 0; r < 4; r++) acc[mi][ni][r] = 0.f;

    prefA(0, 0);
    #pragma unroll
    for (int j = 0; j < 4; j++) {
        float4 v0, v1;
        ldgB(0, j, v0, v1);
        stsB(0, j, v0, v1);
    }
    asm volatile("cp.async.wait_group 0;");
    __syncthreads();

    for (int i = 0; i < nk; i++) {
        uint32_t st = smem_b + (i & 1) * HSTAGE * 2;
        const uint32_t sA = st, sB = st + HA_PLANE * 2;
        const int nxt = (i + 1) & 1;
        const bool more = (i + 1 < nk);
        float4 v0a, v1a, v0b, v1b;
        if (more) {
            prefA(i + 1, nxt);
            ldgB(i + 1, 0, v0a, v1a);
            ldgB(i + 1, 1, v0b, v1b);
        }
        mma_step64(sA, sB, 0,  wm, wn, lane, acc);
        mma_step64(sA, sB, 16, wm, wn, lane, acc);
        if (more) {
            stsB(nxt, 0, v0a, v1a);
            stsB(nxt, 1, v0b, v1b);
            ldgB(i + 1, 2, v0a, v1a);
            ldgB(i + 1, 3, v0b, v1b);
        }
        mma_step64(sA, sB, 32, wm, wn, lane, acc);
        mma_step64(sA, sB, 48, wm, wn, lane, acc);
        if (more) {
            stsB(nxt, 2, v0a, v1a);
            stsB(nxt, 3, v0b, v1b);
            asm volatile("cp.async.wait_group 0;");
        }
        __syncthreads();
    }

    const int g = lane >> 2, tg = lane & 3;
    #pragma unroll
    for (int mi = 0; mi < 4; mi++)
        #pragma unroll
        for (int ni = 0; ni < 4; ni++) {
            int mloc = wm * 64 + mi * 16 + g;
            int col = n0 + wn * 32 + ni * 8 + tg * 2;
            #pragma unroll
            for (int hh = 0; hh < 2; hh++) {
                int m = m0 + mloc + hh * 8;
                if (m >= M) continue;
                int cr = pairmap[m];
                *(float2*)&Cf[(long long)cr * N + col] =
                    make_float2(acc[mi][ni][2 * hh], acc[mi][ni][2 * hh + 1]);
            }
        }
}

// ---------------- fused RoPE + fp16 convert ----------------
__global__ void rope_split_kernel(const float* __restrict__ qkv,
                                  __half* __restrict__ Out) {
    long long idx = (long long)blockIdx.x * 256 + threadIdx.x;
    if (idx >= (long long)T_ * 768) return;
    int t = (int)(idx / 768), s = (int)(idx % 768);
    if (s < 640) {
        int d, off;
        if (s < 512) { int head = s >> 5; d = s & 31; off = head * 64; }
        else         { int j = s - 512; int head = j >> 5; d = j & 31; off = 1024 + head * 64; }
        long long base = (long long)t * QKVN + off;
        float x1 = qkv[base + d], x2 = qkv[base + d + 32];
        int pos = t & (S_ - 1);
        float freq = expf(-logf(1.0e6f) * (2.0f * d) / 64.0f);
        float sn, cs;
        sincosf((float)pos * freq, &sn, &cs);
        Out[base + d]      = __float2half_rn(x1 * cs - x2 * sn);
        Out[base + d + 32] = __float2half_rn(x2 * cs + x1 * sn);
    } else {
        int j = s - 640;
        long long base = (long long)t * QKVN + 1280 + j * 2;
        Out[base]     = __float2half_rn(qkv[base]);
        Out[base + 1] = __float2half_rn(qkv[base + 1]);
    }
}

// ---------------- fp16 flash attention, double-buffered K/V ----------------
#define ATSTR 72
#define AQ 0
#define AKV0 4608
#define AKVSZ 9216
#define ASMEM ((AKV0 + 2 * AKVSZ) * 2)

__global__ __launch_bounds__(128)
void attn_tc_kernel(const __half* __restrict__ QKV16, __half* __restrict__ O16) {
    const int qt = blockIdx.x, bh = blockIdx.y;
    const int b = bh >> 4, h = bh & 15;
    const int kvh = h >> 2;
    const int q0 = qt * 64;
    const int tid = threadIdx.x, lane = tid & 31, w = tid >> 5;
    const int g = lane >> 2, tg = lane & 3;

    extern __shared__ __half asmem[];
    const uint32_t smb = (uint32_t)__cvta_generic_to_shared(asmem);

    auto prefetch_kv = [&](int kc, int buf) {
        const int k0 = kc * 64;
        #pragma unroll
        for (int t2 = 0; t2 < 2; t2++) {
            const __half* src = QKV16 + (t2 == 0 ? 1024 : 1280) + kvh * 64;
            #pragma unroll
            for (int ii = 0; ii < 4; ii++) {
                int rem = tid + ii * 128;
                int row = rem >> 3, c = rem & 7;
                uint32_t dst = smb + (AKV0 + buf * AKVSZ + t2 * 4608 + row * ATSTR + c * 8) * 2;
                cp16(dst, src + (long long)(b * S_ + k0 + row) * QKVN + c * 8, 16);
            }
        }
        asm volatile("cp.async.commit_group;");
    };

    {
        #pragma unroll
        for (int ii = 0; ii < 4; ii++) {
            int rem = tid + ii * 128;
            int row = rem >> 3, c = rem & 7;
            uint32_t dst = smb + (AQ + row * ATSTR + c * 8) * 2;
            cp16(dst, QKV16 + (long long)(b * S_ + q0 + row) * QKVN + h * 64 + c * 8, 16);
        }
        asm volatile("cp.async.commit_group;");
    }
    prefetch_kv(0, 0);
    asm volatile("cp.async.wait_group 1;");
    __syncthreads();

    uint32_t qf[4][4];
    #pragma unroll
    for (int kk = 0; kk < 4; kk++) {
        uint32_t off = ((w * 16 + (lane & 15)) * ATSTR + kk * 16 + (lane >> 4) * 8) * 2;
        asm volatile("ldmatrix.sync.aligned.m8n8.x4.shared.b16 {%0,%1,%2,%3}, [%4];"
                     : "=r"(qf[kk][0]), "=r"(qf[kk][1]), "=r"(qf[kk][2]), "=r"(qf[kk][3])
                     : "r"(smb + AQ * 2 + off));
    }

    float o[8][4];
    #pragma unroll
    for (int n = 0; n < 8; n++)
        #pragma unroll
        for (int r = 0; r < 4; r++) o[n][r] = 0.f;
    float m0 = -INFINITY, m1 = -INFINITY, l0 = 0.f, l1 = 0.f;

    for (int kc = 0; kc <= qt; kc++) {
        asm volatile("cp.async.wait_group 0;");
        __syncthreads();
        if (kc < qt) prefetch_kv(kc + 1, (kc + 1) & 1);

        const uint32_t sK = smb + (AKV0 + (kc & 1) * AKVSZ) * 2;
        const uint32_t sV = sK + 4608 * 2;

        float sf[8][4];
        #pragma unroll
        for (int n = 0; n < 8; n++)
            #pragma unroll
            for (int r = 0; r < 4; r++) sf[n][r] = 0.f;

        #pragma unroll
        for (int kk = 0; kk < 4; kk++) {
            #pragma unroll
            for (int np = 0; np < 4; np++) {
                uint32_t off = ((np * 16 + (lane & 7) + ((lane >> 4) << 3)) * ATSTR
                                + kk * 16 + ((lane >> 3) & 1) * 8) * 2;
                uint32_t kf[4];
                asm volatile("ldmatrix.sync.aligned.m8n8.x4.shared.b16 {%0,%1,%2,%3}, [%4];"
                             : "=r"(kf[0]), "=r"(kf[1]), "=r"(kf[2]), "=r"(kf[3])
                             : "r"(sK + off));
                MMAH16816(sf[2 * np],     qf[kk], kf);
                MMAH16816(sf[2 * np + 1], qf[kk], kf + 2);
            }
        }

        const float sc = 0.125f;
        if (kc == qt) {
            int r0loc = w * 16 + g, r1loc = r0loc + 8;
            #pragma unroll
            for (int n = 0; n < 8; n++) {
                int c0 = 8 * n + 2 * tg, c1 = c0 + 1;
                sf[n][0] = (c0 <= r0loc) ? sf[n][0] * sc : -INFINITY;
                sf[n][1] = (c1 <= r0loc) ? sf[n][1] * sc : -INFINITY;
                sf[n][2] = (c0 <= r1loc) ? sf[n][2] * sc : -INFINITY;
                sf[n][3] = (c1 <= r1loc) ? sf[n][3] * sc : -INFINITY;
            }
        } else {
            #pragma unroll
            for (int n = 0; n < 8; n++)
                #pragma unroll
                for (int r = 0; r < 4; r++) sf[n][r] *= sc;
        }

        float mx0 = -INFINITY, mx1 = -INFINITY;
        #pragma unroll
        for (int n = 0; n < 8; n++) {
            mx0 = fmaxf(mx0, fmaxf(sf[n][0], sf[n][1]));
            mx1 = fmaxf(mx1, fmaxf(sf[n][2], sf[n][3]));
        }
        mx0 = fmaxf(mx0, __shfl_xor_sync(~0u, mx0, 1));
        mx0 = fmaxf(mx0, __shfl_xor_sync(~0u, mx0, 2));
        mx1 = fmaxf(mx1, __shfl_xor_sync(~0u, mx1, 1));
        mx1 = fmaxf(mx1, __shfl_xor_sync(~0u, mx1, 2));
        float nm0 = fmaxf(m0, mx0), nm1 = fmaxf(m1, mx1);
        float f0 = __expf(m0 - nm0), f1 = __expf(m1 - nm1);
        m0 = nm0; m1 = nm1;
        float s0 = 0.f, s1 = 0.f;
        #pragma unroll
        for (int n = 0; n < 8; n++) {
            float p;
            p = __expf(sf[n][0] - nm0); sf[n][0] = p; s0 += p;
            p = __expf(sf[n][1] - nm0); sf[n][1] = p; s0 += p;
            p = __expf(sf[n][2] - nm1); sf[n][2] = p; s1 += p;
            p = __expf(sf[n][3] - nm1); sf[n][3] = p; s1 += p;
        }
        s0 += __shfl_xor_sync(~0u, s0, 1); s0 += __shfl_xor_sync(~0u, s0, 2);
        s1 += __shfl_xor_sync(~0u, s1, 1); s1 += __shfl_xor_sync(~0u, s1, 2);
        l0 = l0 * f0 + s0;
        l1 = l1 * f1 + s1;
        #pragma unroll
        for (int n = 0; n < 8; n++) {
            o[n][0] *= f0; o[n][1] *= f0; o[n][2] *= f1; o[n][3] *= f1;
        }

        #pragma unroll
        for (int kk = 0; kk < 4; kk++) {
            uint32_t pa[4];
            {
                float* c0 = sf[2 * kk];
                float* c1 = sf[2 * kk + 1];
                __half2 p0 = __floats2half2_rn(c0[0], c0[1]);
                __half2 p1 = __floats2half2_rn(c0[2], c0[3]);
                __half2 p2 = __floats2half2_rn(c1[0], c1[1]);
                __half2 p3 = __floats2half2_rn(c1[2], c1[3]);
                pa[0] = *(uint32_t*)&p0;
                pa[1] = *(uint32_t*)&p1;
                pa[2] = *(uint32_t*)&p2;
                pa[3] = *(uint32_t*)&p3;
            }
            #pragma unroll
            for (int dp = 0; dp < 4; dp++) {
                uint32_t off = ((kk * 16 + (lane & 15)) * ATSTR + dp * 16 + (lane >> 4) * 8) * 2;
                uint32_t vf[4];
                asm volatile("ldmatrix.sync.aligned.m8n8.x4.trans.shared.b16 {%0,%1,%2,%3}, [%4];"
                             : "=r"(vf[0]), "=r"(vf[1]), "=r"(vf[2]), "=r"(vf[3])
                             : "r"(sV + off));
                MMAH16816(o[2 * dp],     pa, vf);
                MMAH16816(o[2 * dp + 1], pa, vf + 2);
            }
        }
    }

    float il0 = 1.f / l0, il1 = 1.f / l1;
    int row0 = q0 + w * 16 + g, row1 = row0 + 8;
    #pragma unroll
    for (int n = 0; n < 8; n++) {
        int col = 8 * n + 2 * tg;
        long long i0 = ((long long)(b * S_ + row0) * NH_ + h) * 64 + col;
        long long i1 = ((long long)(b * S_ + row1) * NH_ + h) * 64 + col;
        *(__half2*)&O16[i0] = __floats2half2_rn(o[n][0] * il0, o[n][1] * il0);
        *(__half2*)&O16[i1] = __floats2half2_rn(o[n][2] * il1, o[n][3] * il1);
    }
}

// ---------------- router ----------------
__global__ void reset_kernel(int* cnt) {
    if (threadIdx.x < E_) cnt[threadIdx.x] = 0;
}

__global__ void router_kernel(const float* __restrict__ Xn, const float* __restrict__ RW,
                              int* __restrict__ cnt, int* __restrict__ tok,
                              int* __restrict__ pairm, float* __restrict__ pairw) {
    int t = blockIdx.x * 4 + (threadIdx.x >> 5);
    int lane = threadIdx.x & 31;
    if (t >= T_) return;
    float acc[E_];
    #pragma unroll
    for (int e = 0; e < E_; e++) acc[e] = 0.f;
    const float* x = Xn + (long long)t * H_;
    for (int k = lane; k < H_; k += 32) {
        float xv = x[k];
        #pragma unroll
        for (int e = 0; e < E_; e++) acc[e] = fmaf(xv, RW[k * E_ + e], acc[e]);
    }
    #pragma unroll
    for (int e = 0; e < E_; e++)
        #pragma unroll
        for (int o = 16; o; o >>= 1) acc[e] += __shfl_xor_sync(~0u, acc[e], o);
    if (lane == 0) {
        float mx = acc[0];
        #pragma unroll
        for (int e = 1; e < E_; e++) mx = fmaxf(mx, acc[e]);
        float p[E_], s = 0.f;
        #pragma unroll
        for (int e = 0; e < E_; e++) { p[e] = expf(acc[e] - mx); s += p[e]; }
        #pragma unroll
        for (int e = 0; e < E_; e++) p[e] /= s;
        int i0 = 0; float v0 = p[0];
        #pragma unroll
        for (int e = 1; e < E_; e++) if (p[e] > v0) { v0 = p[e]; i0 = e; }
        int i1 = -1; float v1 = -1.f;
        #pragma unroll
        for (int e = 0; e < E_; e++) if (e != i0 && p[e] > v1) { v1 = p[e]; i1 = e; }
        if (i1 < 0) i1 = i0 ? 0 : 1;
        float tw = v0 + v1;
        pairw[t * 2]     = v0 / tw;
        pairw[t * 2 + 1] = v1 / tw;
        int r0 = atomicAdd(&cnt[i0], 1);
        tok[i0 * T_ + r0] = t; pairm[i0 * T_ + r0] = t * 2;
        int r1 = atomicAdd(&cnt[i1], 1);
        tok[i1 * T_ + r1] = t; pairm[i1 * T_ + r1] = t * 2 + 1;
    }
}

// ---------------- combine ----------------
__global__ void combine_kernel(const float* __restrict__ hidden, const float* __restrict__ down,
                               const float* __restrict__ pairw, float* __restrict__ out) {
    long long i = (long long)blockIdx.x * 256 + threadIdx.x;
    if (i >= (long long)T_ * H_) return;
    int t = (int)(i >> 10);
    int hh = (int)(i & 1023);
    out[i] = hidden[i]
           + pairw[t * 2]     * down[((long long)t * 2)     * H_ + hh]
           + pairw[t * 2 + 1] * down[((long long)t * 2 + 1) * H_ + hh];
}

// ---------------- launcher ----------------
extern "C" void kernel_launch(void* const* d_in, const int* in_sizes, int n_in,
                              void* d_out, int out_size) {
    const float* hs    = (const float*)d_in[0];
    const float* ln1   = (const float*)d_in[2];
    const float* ln2   = (const float*)d_in[3];
    const float* wq    = (const float*)d_in[4];
    const float* wk    = (const float*)d_in[5];
    const float* wv    = (const float*)d_in[6];
    const float* wo    = (const float*)d_in[7];
    const float* rw    = (const float*)d_in[8];
    const float* wgate = (const float*)d_in[9];
    const float* wup   = (const float*)d_in[10];
    const float* wdown = (const float*)d_in[11];
    float* out = (float*)d_out;

    float *pqkv, *phid, *pxn, *pdowno, *ppw;
    int *pcnt, *ptok, *ppm;
    __half *x16, *qkv16, *wqkv16, *at16, *wo16, *xn16, *act16;
    cudaGetSymbolAddress((void**)&pqkv,   g_qkv);
    cudaGetSymbolAddress((void**)&phid,   g_hidden);
    cudaGetSymbolAddress((void**)&pxn,    g_xn);
    cudaGetSymbolAddress((void**)&pdowno, g_downo);
    cudaGetSymbolAddress((void**)&ppw,    g_pairw);
    cudaGetSymbolAddress((void**)&pcnt,   g_cnt);
    cudaGetSymbolAddress((void**)&ptok,   g_tok);
    cudaGetSymbolAddress((void**)&ppm,    g_pairm);
    cudaGetSymbolAddress((void**)&x16,   h_x);
    cudaGetSymbolAddress((void**)&qkv16, h_qkv);
    cudaGetSymbolAddress((void**)&wqkv16, h_wqkv);
    cudaGetSymbolAddress((void**)&at16, h_at);
    cudaGetSymbolAddress((void**)&wo16, h_wo);
    cudaGetSymbolAddress((void**)&xn16, h_xn);
    cudaGetSymbolAddress((void**)&act16, h_act);

    cudaFuncSetAttribute(gemm_h_kernel, cudaFuncAttributeMaxDynamicSharedMemorySize, HSMEM2);
    cudaFuncSetAttribute(gemm_gu32_kernel, cudaFuncAttributeMaxDynamicSharedMemorySize, HSMEM2);
    cudaFuncSetAttribute(gemm_d32_kernel, cudaFuncAttributeMaxDynamicSharedMemorySize, HSMEM2);
    cudaFuncSetAttribute(attn_tc_kernel, cudaFuncAttributeMaxDynamicSharedMemorySize, ASMEM);

    // ---- merged small weight conversion (qkv pack + wo), one launch ----
    long long nconv = (long long)NQW + 2 * NKW + NQW;
    convw_kernel<<<(int)((nconv / 4 + 255) / 256), 256>>>(wq, wk, wv, wo, wqkv16, wo16);

    // 1) ln1 -> fp16
    rmsnorm_kernel<<<T_, 256>>>(hs, ln1, nullptr, x16);
    // 2) combined QKV projection (fp16 HMMA, fp32 out)
    gemm_h_kernel<<<dim3(QKVN / GBN, T_ / GBM, 1), 256, HSMEM2>>>(
        x16, wqkv16, pqkv, nullptr, T_, QKVN, H_);
    // 3) fused RoPE + fp16 convert (separate elementwise pass — latency-tolerant)
    rope_split_kernel<<<(int)(((long long)T_ * 768 + 255) / 256), 256>>>(pqkv, qkv16);
    // 4) attention
    attn_tc_kernel<<<dim3(S_ / 64, B_ * NH_), 128, ASMEM>>>(qkv16, at16);
    // 5) out projection + residual
    gemm_h_kernel<<<dim3(H_ / GBN, T_ / GBM, 1), 256, HSMEM2>>>(
        at16, wo16, phid, hs, T_, H_, NH_ * HD_);
    // 6) ln2
    rmsnorm_kernel<<<T_, 256>>>(phid, ln2, pxn, xn16);
    // 7) router + grouping
    reset_kernel<<<1, 32>>>(pcnt);
    router_kernel<<<T_ / 4, 128>>>(pxn, rw, pcnt, ptok, ppm, ppw);
    // 8) MoE fused gate+up, B read as fp32
    gemm_gu32_kernel<<<dim3(I_ / 64, T_ / GBM, E_), 256, HSMEM2>>>(
        xn16, wgate, wup, act16, I_, H_, pcnt, ptok, ppm, (long long)H_ * I_);
    // 9) down projection, B read as fp32
    gemm_d32_kernel<<<dim3(H_ / GBN, T_ / GBM, E_), 256, HSMEM2>>>(
        act16, wdown, pdowno, H_, I_, pcnt, ppm, ppm, (long long)I_ * H_);
    // 10) combine
    combine_kernel<<<(T_ * H_ + 255) / 256, 256>>>(phid, pdowno, ppw, out);
}